// round 13
// baseline (speedup 1.0000x reference)
#include <cuda_runtime.h>
#include <cuda_fp16.h>
#include <cstdint>

// Problem constants
#define B_      32
#define C_      8
#define H_      224
#define W_      224
#define E_      768
#define P_      16
#define HP_     14
#define NPATCH  196
#define NSEG    32
#define K_      256
#define M_      (B_*C_*NPATCH)  // 50176

// Static device scratch
__device__ __half g_xh[B_*C_*H_*W_];   // x as half
__device__ __half g_Bh[E_*K_];         // proj_w as half
__device__ float g_part[512*K_];       // per-(bc, w-half) partial pixel sums
__device__ float g_xm[NSEG*K_];        // segment-mean patch pixels
__device__ float g_mu[NSEG*E_];        // segment-mean embeddings (+proj_b)
__device__ float g_ctx[NSEG*E_];       // context vectors

// ---------------------------------------------------------------------------
static __device__ __forceinline__ uint32_t smem_u32(const void* p) {
    uint32_t a;
    asm("{ .reg .u64 t; cvta.to.shared.u64 t, %1; cvt.u32.u64 %0, t; }" : "=r"(a) : "l"(p));
    return a;
}
static __device__ __forceinline__ void cpa16(uint32_t dst, const void* src) {
    asm volatile("cp.async.cg.shared.global [%0], [%1], 16;" :: "r"(dst), "l"(src));
}
static __device__ __forceinline__ void cp_commit() {
    asm volatile("cp.async.commit_group;" ::: "memory");
}
static __device__ __forceinline__ void cp_wait2() {
    asm volatile("cp.async.wait_group 2;" ::: "memory");
}
static __device__ __forceinline__ void ldmx4(uint32_t* r, uint32_t a) {
    asm volatile("ldmatrix.sync.aligned.m8n8.x4.shared.b16 {%0,%1,%2,%3}, [%4];"
                 : "=r"(r[0]), "=r"(r[1]), "=r"(r[2]), "=r"(r[3]) : "r"(a));
}
static __device__ __forceinline__ void mma_f16(float* c, const uint32_t* a, const uint32_t* b) {
    asm volatile("mma.sync.aligned.m16n8k16.row.col.f32.f16.f16.f32 "
                 "{%0,%1,%2,%3}, {%4,%5,%6,%7}, {%8,%9}, {%0,%1,%2,%3};"
                 : "+f"(c[0]), "+f"(c[1]), "+f"(c[2]), "+f"(c[3])
                 : "r"(a[0]), "r"(a[1]), "r"(a[2]), "r"(a[3]), "r"(b[0]), "r"(b[1]));
}
// swizzled byte offset of 16B-granule g (0..31) within a 512B full-K row
static __device__ __forceinline__ uint32_t swg32(int r, int g) {
    return (uint32_t)(r * 512 + (((g & 24) | ((g ^ r) & 7)) << 4));
}

// ---------------------------------------------------------------------------
// Launch 0: fused x->half conversion + patch-position partial sums.
// Grid 512 (= bc*2 + w-half z). Thread t = p*16 + q4*4 + hpg.
__global__ void k_prepx(const float* __restrict__ x) {
    int bc = blockIdx.x >> 1;
    int z  = blockIdx.x & 1;
    int t  = threadIdx.x;
    int p = t >> 4, q4 = (t >> 2) & 3, hpg = t & 3;
    const float* xb = x + (size_t)bc * H_ * W_;
    __half* xhb = g_xh + (size_t)bc * H_ * W_;
    float a0 = 0.f, a1 = 0.f, a2 = 0.f, a3 = 0.f;
    #pragma unroll
    for (int i = 0; i < 4; i++) {
        int hp = hpg + i * 4;
        if (hp < HP_) {
            int h = hp * P_ + p;
            #pragma unroll
            for (int jj = 0; jj < 7; jj++) {
                int w = (q4 + 4 * (z * 7 + jj)) * 4;
                float4 v = *(const float4*)(xb + h * W_ + w);
                __half2 h01 = __floats2half2_rn(v.x, v.y);
                __half2 h23 = __floats2half2_rn(v.z, v.w);
                uint2 pk;
                pk.x = *(uint32_t*)&h01;
                pk.y = *(uint32_t*)&h23;
                *(uint2*)(xhb + h * W_ + w) = pk;
                a0 += v.x; a1 += v.y; a2 += v.z; a3 += v.w;
            }
        }
    }
    // reduce over hpg (lanes differing in bits 0-1)
    #pragma unroll
    for (int d = 1; d < 4; d <<= 1) {
        a0 += __shfl_xor_sync(0xFFFFFFFF, a0, d);
        a1 += __shfl_xor_sync(0xFFFFFFFF, a1, d);
        a2 += __shfl_xor_sync(0xFFFFFFFF, a2, d);
        a3 += __shfl_xor_sync(0xFFFFFFFF, a3, d);
    }
    if (hpg == 0) {
        float4 o = {a0, a1, a2, a3};
        *(float4*)(g_part + (size_t)blockIdx.x * K_ + p * 16 + q4 * 4) = o;
    }
}

// Launch 1: proj_w -> half (8 elems/thread)
__global__ void k_tohalf(const float* __restrict__ src, __half* __restrict__ dst) {
    size_t i = ((size_t)blockIdx.x * 256 + threadIdx.x) * 8;
    float4 v0 = *(const float4*)(src + i);
    float4 v1 = *(const float4*)(src + i + 4);
    __half2 h[4];
    h[0] = __floats2half2_rn(v0.x, v0.y);
    h[1] = __floats2half2_rn(v0.z, v0.w);
    h[2] = __floats2half2_rn(v1.x, v1.y);
    h[3] = __floats2half2_rn(v1.z, v1.w);
    *(uint4*)(dst + i) = *(uint4*)h;
}

// Launch 2: gather-based segment means; ballot-prefix list build. Grid 32.
__global__ void k_seg(const int* __restrict__ cidx) {
    __shared__ unsigned wmask[8];
    __shared__ int list[B_*C_];
    int t = threadIdx.x, lane = t & 31, w = t >> 5;
    int seg = blockIdx.x;
    int mine = cidx[t] & (NSEG-1);     // B_*C_ == 256 == blockDim
    unsigned m = __ballot_sync(0xFFFFFFFF, mine == seg);
    if (lane == 0) wmask[w] = m;
    __syncthreads();
    int off = 0, total = 0;
    #pragma unroll
    for (int i = 0; i < 8; i++) {
        int pc = __popc(wmask[i]);
        if (i < w) off += pc;
        total += pc;
    }
    if (mine == seg)
        list[off + __popc(m & ((1u << lane) - 1))] = t;
    __syncthreads();
    float s = 0.f;
    for (int j = 0; j < total; j++) {   // independent coalesced loads, high MLP
        int bc = list[j];
        s += g_part[(2*bc)*K_ + t] + g_part[(2*bc+1)*K_ + t];
    }
    g_xm[seg*K_ + t] = s / ((float)NPATCH * fmaxf((float)total, 1.f));
}

// Launch 3: mu[s,e] = xm[s,:]@proj_w[e,:] + proj_b[e]. Grid 96 x 256.
__global__ void k_mu2(const float* __restrict__ proj_w, const float* __restrict__ proj_b) {
    __shared__ float xs[NSEG*257];
    int t = threadIdx.x;
    for (int i = t; i < NSEG*K_; i += 256) xs[(i >> 8)*257 + (i & 255)] = g_xm[i];
    __syncthreads();
    int s = t & 31;
    int e = blockIdx.x * 8 + (t >> 5);
    const float* wrow = proj_w + (size_t)e * K_;   // uniform per warp
    float acc = 0.f;
    #pragma unroll 8
    for (int k = 0; k < K_; k++) acc += xs[s*257 + k] * wrow[k];
    g_mu[s*E_ + e] = acc + proj_b[e];
}

// Launch 4: ctx[s,e] = mu[s,:]@ctx_w[e,:] + ctx_b[e]. Grid 96 x 256.
__global__ void k_ctx3(const float* __restrict__ ctx_w, const float* __restrict__ ctx_b) {
    extern __shared__ float mus[];   // [32][769] padded
    int t = threadIdx.x;
    for (int i = t; i < NSEG*E_; i += 256) {
        int s = i / E_, f = i - s * E_;
        mus[s*769 + f] = g_mu[i];
    }
    __syncthreads();
    int s = t & 31;
    int e = blockIdx.x * 8 + (t >> 5);
    const float* crow = ctx_w + (size_t)e * E_;    // uniform per warp
    float acc = 0.f;
    #pragma unroll 8
    for (int f = 0; f < E_; f++) acc += mus[s*769 + f] * crow[f];
    g_ctx[s*E_ + e] = acc + ctx_b[e];
}

// ---------------------------------------------------------------------------
// Launch 5: FP16 mma.sync GEMM, B-resident. CTA 128x128, K=256.
// SMEM: B full-K 64KB (loaded once) + A 3x16KB pipelined stages = 112KB. 2 CTAs/SM.
#define BM 128
#define BN 128
#define NCH 4
#define B_BYTES 65536
#define A_STG 16384
#define SMEM_TOT (B_BYTES + 3*A_STG)   // 114688

__global__ __launch_bounds__(256, 2)
void k_gemm_mma(const int* __restrict__ cidx, const float* __restrict__ proj_b,
                float* __restrict__ out) {
    extern __shared__ char dsm[];
    int t = threadIdx.x;
    int lane = t & 31;
    int wid = t >> 5;
    int wm = wid >> 1, wn = wid & 1;
    int m0 = blockIdx.y * BM;
    int e0 = blockIdx.x * BN;
    uint32_t sB  = smem_u32(dsm);
    uint32_t sA0 = sB + B_BYTES;

    // --- B: full-K panel, 16 granules per thread, max MLP upfront ---
    #pragma unroll
    for (int j = 0; j < 16; j++) {
        int idx = t + 256 * j;
        int row = idx >> 5, g = idx & 31;
        cpa16(sB + swg32(row, g), g_Bh + (size_t)(e0 + row) * K_ + g * 8);
    }

    // --- A: per-thread copy descriptors (4 fixed rows, fixed granule gA) ---
    int gA = t & 7;
    const __half* aptr[4];
    uint32_t adst[4];
    #pragma unroll
    for (int j = 0; j < 4; j++) {
        int row = (t >> 3) + 32 * j;
        int m = m0 + row;
        int b  = m / (C_ * NPATCH);
        int n  = m - b * (C_ * NPATCH);
        int cc = n / NPATCH;
        int r  = n - cc * NPATCH;
        int hp = r / HP_;
        int wp = r - hp * HP_;
        aptr[j] = g_xh + ((b * C_ + cc) * H_ + hp * P_) * W_ + wp * P_
                       + (gA >> 1) * W_ + (gA & 1) * 8;
        adst[j] = (uint32_t)(row * 128 + ((gA ^ (row & 7)) << 4));
    }
    auto issueA = [&](int c, int st) {
        uint32_t base = sA0 + st * A_STG;
        #pragma unroll
        for (int j = 0; j < 4; j++)
            cpa16(base + adst[j], aptr[j] + c * 4 * W_);   // chunk c: pixel rows 4c..4c+3
    };

    issueA(0, 0); cp_commit();   // group0 = B + A0
    issueA(1, 1); cp_commit();
    issueA(2, 2); cp_commit();

    float acc[2][8][4];
    #pragma unroll
    for (int i = 0; i < 2; i++)
        #pragma unroll
        for (int j = 0; j < 8; j++)
            #pragma unroll
            for (int s = 0; s < 4; s++) acc[i][j][s] = 0.f;

    int gid = lane >> 2, tid = lane & 3;

    for (int c = 0; c < NCH; c++) {
        int st = c % 3;
        cp_wait2();
        __syncthreads();

        uint32_t sa = sA0 + st * A_STG;
        #pragma unroll
        for (int ks = 0; ks < 4; ks++) {
            uint32_t a[2][4];
            #pragma unroll
            for (int i = 0; i < 2; i++) {
                int r = wm * 32 + i * 16 + (lane & 15);
                int g = 2 * ks + (lane >> 4);
                ldmx4(a[i], sa + r * 128 + ((g ^ (r & 7)) << 4));
            }
            uint32_t b[8][2];
            #pragma unroll
            for (int j = 0; j < 4; j++) {
                int nt = 2 * j + ((lane >> 4) & 1);
                int n = wn * 64 + nt * 8 + (lane & 7);
                int g = 8 * c + 2 * ks + ((lane >> 3) & 1);   // full-K granule index
                uint32_t r4[4];
                ldmx4(r4, sB + swg32(n, g));
                b[2*j][0] = r4[0]; b[2*j][1] = r4[1];
                b[2*j+1][0] = r4[2]; b[2*j+1][1] = r4[3];
            }
            #pragma unroll
            for (int i = 0; i < 2; i++)
                #pragma unroll
                for (int j = 0; j < 8; j++)
                    mma_f16(acc[i][j], a[i], b[j]);
        }
        __syncthreads();
        if (c + 3 < NCH) issueA(c + 3, st);
        cp_commit();   // empty groups keep wait_group arithmetic uniform
    }

    // Epilogue: c0,c1 @ row gid; c2,c3 @ row gid+8; cols 2*tid
    #pragma unroll
    for (int i = 0; i < 2; i++) {
        #pragma unroll
        for (int h = 0; h < 2; h++) {
            int mloc = wm * 32 + i * 16 + h * 8 + gid;
            int m = m0 + mloc;
            int seg = cidx[m / NPATCH] & (NSEG-1);
            const float* cr = g_ctx + (size_t)seg * E_;
            float* orow = out + (size_t)m * E_;
            #pragma unroll
            for (int j = 0; j < 8; j++) {
                int col = e0 + wn * 64 + j * 8 + tid * 2;
                float2 bv = *(const float2*)(proj_b + col);
                float2 cv = *(const float2*)(cr + col);
                float2 o;
                o.x = acc[i][j][h*2+0] + bv.x + cv.x;
                o.y = acc[i][j][h*2+1] + bv.y + cv.y;
                *(float2*)(orow + col) = o;
            }
        }
    }
}

// ---------------------------------------------------------------------------
extern "C" void kernel_launch(void* const* d_in, const int* in_sizes, int n_in,
                              void* d_out, int out_size) {
    const float* x      = (const float*)d_in[0];
    const int*   cidx   = (const int*)d_in[1];
    const float* proj_w = (const float*)d_in[2];
    const float* proj_b = (const float*)d_in[3];
    const float* ctx_w  = (const float*)d_in[4];
    const float* ctx_b  = (const float*)d_in[5];
    float*       out    = (float*)d_out;

    __half* bh; cudaGetSymbolAddress((void**)&bh, g_Bh);

    k_prepx<<<2*B_*C_, 256>>>(x);                          // 0 (fused tohalf+xbar)
    k_tohalf<<<(E_*K_)/2048, 256>>>(proj_w, bh);           // 1
    k_seg<<<NSEG, 256>>>(cidx);                            // 2
    k_mu2<<<E_/8, 256>>>(proj_w, proj_b);                  // 3

    cudaFuncSetAttribute(k_ctx3, cudaFuncAttributeMaxDynamicSharedMemorySize, NSEG*769*4);
    k_ctx3<<<E_/8, 256, NSEG*769*4>>>(ctx_w, ctx_b);       // 4

    cudaFuncSetAttribute(k_gemm_mma, cudaFuncAttributeMaxDynamicSharedMemorySize, SMEM_TOT);
    k_gemm_mma<<<dim3(E_/BN, M_/BM), 256, SMEM_TOT>>>(cidx, proj_b, out);  // 5
}

// round 14
// speedup vs baseline: 1.2929x; 1.2929x over previous
#include <cuda_runtime.h>
#include <cuda_fp16.h>
#include <cstdint>

// Problem constants
#define B_      32
#define C_      8
#define H_      224
#define W_      224
#define E_      768
#define P_      16
#define HP_     14
#define NPATCH  196
#define NSEG    32
#define K_      256
#define M_      (B_*C_*NPATCH)  // 50176

// Static device scratch
__device__ __half g_xh[B_*C_*H_*W_];   // x as half
__device__ __half g_Bh[E_*K_];         // proj_w as half
__device__ float g_part[512*K_];       // per-(bc, w-half) partial pixel sums
__device__ float g_xm[NSEG*K_];        // segment-mean patch pixels
__device__ float g_mu[NSEG*E_];        // segment-mean embeddings (+proj_b)
__device__ float g_ctx[NSEG*E_];       // context vectors

// ---------------------------------------------------------------------------
static __device__ __forceinline__ uint32_t smem_u32(const void* p) {
    uint32_t a;
    asm("{ .reg .u64 t; cvta.to.shared.u64 t, %1; cvt.u32.u64 %0, t; }" : "=r"(a) : "l"(p));
    return a;
}
static __device__ __forceinline__ void cpa16(uint32_t dst, const void* src) {
    asm volatile("cp.async.cg.shared.global [%0], [%1], 16;" :: "r"(dst), "l"(src));
}
static __device__ __forceinline__ void cp_commit() {
    asm volatile("cp.async.commit_group;" ::: "memory");
}
static __device__ __forceinline__ void cp_wait2() {
    asm volatile("cp.async.wait_group 2;" ::: "memory");
}
static __device__ __forceinline__ void ldmx4(uint32_t* r, uint32_t a) {
    asm volatile("ldmatrix.sync.aligned.m8n8.x4.shared.b16 {%0,%1,%2,%3}, [%4];"
                 : "=r"(r[0]), "=r"(r[1]), "=r"(r[2]), "=r"(r[3]) : "r"(a));
}
static __device__ __forceinline__ void mma_f16(float* c, const uint32_t* a, const uint32_t* b) {
    asm volatile("mma.sync.aligned.m16n8k16.row.col.f32.f16.f16.f32 "
                 "{%0,%1,%2,%3}, {%4,%5,%6,%7}, {%8,%9}, {%0,%1,%2,%3};"
                 : "+f"(c[0]), "+f"(c[1]), "+f"(c[2]), "+f"(c[3])
                 : "r"(a[0]), "r"(a[1]), "r"(a[2]), "r"(a[3]), "r"(b[0]), "r"(b[1]));
}

// ---------------------------------------------------------------------------
// Launch 0/1: float -> half conversion (8 elems/thread)
__global__ void k_tohalf(const float* __restrict__ src, __half* __restrict__ dst) {
    size_t i = ((size_t)blockIdx.x * 256 + threadIdx.x) * 8;
    float4 v0 = *(const float4*)(src + i);
    float4 v1 = *(const float4*)(src + i + 4);
    __half2 h[4];
    h[0] = __floats2half2_rn(v0.x, v0.y);
    h[1] = __floats2half2_rn(v0.z, v0.w);
    h[2] = __floats2half2_rn(v1.x, v1.y);
    h[3] = __floats2half2_rn(v1.z, v1.w);
    *(uint4*)(dst + i) = *(uint4*)h;
}

// Launch 2: per-(bc, half-range) pixel sums from g_xh.
__global__ void k_xbar() {
    int bc = blockIdx.x >> 1;
    int z  = blockIdx.x & 1;
    int t = threadIdx.x;
    int p = t >> 4, q = t & 15;
    const __half* base = g_xh + (size_t)bc * H_ * W_ + p * W_ + q;
    float s = 0.f;
    for (int hp = z*7; hp < z*7 + 7; hp++)
        #pragma unroll
        for (int wp = 0; wp < HP_; wp++)
            s += __half2float(base[(hp*P_)*W_ + wp*P_]);
    g_part[blockIdx.x * K_ + t] = s;
}

// Launch 3: gather-based segment means; ballot-prefix list build. Grid 32.
__global__ void k_seg(const int* __restrict__ cidx) {
    __shared__ unsigned wmask[8];
    __shared__ int list[B_*C_];
    int t = threadIdx.x, lane = t & 31, w = t >> 5;
    int seg = blockIdx.x;
    int mine = cidx[t] & (NSEG-1);     // B_*C_ == 256 == blockDim
    unsigned m = __ballot_sync(0xFFFFFFFF, mine == seg);
    if (lane == 0) wmask[w] = m;
    __syncthreads();
    int off = 0, total = 0;
    #pragma unroll
    for (int i = 0; i < 8; i++) {
        int pc = __popc(wmask[i]);
        if (i < w) off += pc;
        total += pc;
    }
    if (mine == seg)
        list[off + __popc(m & ((1u << lane) - 1))] = t;
    __syncthreads();
    float s = 0.f;
    for (int j = 0; j < total; j++) {   // independent coalesced loads, high MLP
        int bc = list[j];
        s += g_part[(2*bc)*K_ + t] + g_part[(2*bc+1)*K_ + t];
    }
    g_xm[seg*K_ + t] = s / ((float)NPATCH * fmaxf((float)total, 1.f));
}

// Launch 4: mu[s,e] = xm[s,:]@proj_w[e,:] + proj_b[e]. Warp per output.
// Grid 3072 x 256 (8 warps/block, 24576 warps = 32*768 outputs).
__global__ void k_mu3(const float* __restrict__ proj_w, const float* __restrict__ proj_b) {
    int gw = (blockIdx.x * 256 + threadIdx.x) >> 5;
    int lane = threadIdx.x & 31;
    int s = gw & 31;
    int e = gw >> 5;
    const float* xm = g_xm + s * K_ + lane * 8;
    const float* wr = proj_w + (size_t)e * K_ + lane * 8;
    float4 x0 = *(const float4*)xm;
    float4 x1 = *(const float4*)(xm + 4);
    float4 w0 = *(const float4*)wr;
    float4 w1 = *(const float4*)(wr + 4);
    float acc = x0.x*w0.x + x0.y*w0.y + x0.z*w0.z + x0.w*w0.w
              + x1.x*w1.x + x1.y*w1.y + x1.z*w1.z + x1.w*w1.w;
    #pragma unroll
    for (int d = 16; d > 0; d >>= 1)
        acc += __shfl_xor_sync(0xFFFFFFFF, acc, d);
    if (lane == 0) g_mu[s * E_ + e] = acc + proj_b[e];
}

// Launch 5: ctx[s,e] = mu[s,:]@ctx_w[e,:] + ctx_b[e]. Warp per output. Grid 3072 x 256.
__global__ void k_ctx4(const float* __restrict__ ctx_w, const float* __restrict__ ctx_b) {
    int gw = (blockIdx.x * 256 + threadIdx.x) >> 5;
    int lane = threadIdx.x & 31;
    int s = gw & 31;
    int e = gw >> 5;
    const float* mr = g_mu + s * E_;
    const float* cr = ctx_w + (size_t)e * E_;
    float acc = 0.f;
    #pragma unroll
    for (int c = 0; c < 6; c++) {         // f = c*128 + lane*4, coalesced float4
        int f = c * 128 + lane * 4;
        float4 mv = *(const float4*)(mr + f);
        float4 cv = *(const float4*)(cr + f);
        acc += mv.x*cv.x + mv.y*cv.y + mv.z*cv.z + mv.w*cv.w;
    }
    #pragma unroll
    for (int d = 16; d > 0; d >>= 1)
        acc += __shfl_xor_sync(0xFFFFFFFF, acc, d);
    if (lane == 0) g_ctx[s * E_ + e] = acc + ctx_b[e];
}

// ---------------------------------------------------------------------------
// Launch 6: FP16 mma.sync GEMM. CTA 128x128, K=256 in 4 chunks of 64.
// Stage: A 128x128B + B 128x128B = 32KB; 3 stages; XOR-swizzled 16B granules.
// (R12 configuration — best measured.)
#define BM 128
#define BN 128
#define CK 64
#define NCH 4
#define ROWB 128
#define A_BYTES (BM*ROWB)     // 16384
#define STG_B (2*A_BYTES)     // 32768
#define NSTG 3

__global__ __launch_bounds__(256, 2)
void k_gemm_mma(const int* __restrict__ cidx, const float* __restrict__ proj_b,
                float* __restrict__ out) {
    extern __shared__ char dsm[];
    __shared__ int rowoff[BM];
    __shared__ int segrow[BM];

    int t = threadIdx.x;
    int lane = t & 31;
    int wid = t >> 5;
    int wm = wid >> 1, wn = wid & 1;
    int m0 = blockIdx.y * BM;
    int e0 = blockIdx.x * BN;
    uint32_t base_u = smem_u32(dsm);

    if (t < BM) {
        int m  = m0 + t;
        int b  = m / (C_ * NPATCH);
        int n  = m - b * (C_ * NPATCH);
        int c  = n / NPATCH;
        int r  = n - c * NPATCH;
        int hp = r / HP_;
        int wp = r - hp * HP_;
        rowoff[t] = ((b * C_ + c) * H_ + hp * P_) * W_ + wp * P_;
        segrow[t] = cidx[m / NPATCH] & (NSEG-1);
    }
    __syncthreads();

    // chunk c covers local k = 0..63 : pixel rows 4c..4c+3, 16 halves each.
    auto issue = [&](int c, int st) {
        uint32_t sb = base_u + st * STG_B;
        #pragma unroll
        for (int j = 0; j < 4; j++) {
            int idx = t + 256 * j;
            int row = idx >> 3, g = idx & 7;
            uint32_t sw = (uint32_t)((g ^ (row & 7)) << 4);
            const __half* pa = g_xh + rowoff[row] + (c*4 + (g >> 1)) * W_ + (g & 1) * 8;
            cpa16(sb + row * ROWB + sw, pa);
            const __half* pb = g_Bh + (size_t)(e0 + row) * K_ + c * CK + g * 8;
            cpa16(sb + A_BYTES + row * ROWB + sw, pb);
        }
    };

    issue(0, 0); cp_commit();
    issue(1, 1); cp_commit();
    issue(2, 2); cp_commit();

    float acc[2][8][4];
    #pragma unroll
    for (int i = 0; i < 2; i++)
        #pragma unroll
        for (int j = 0; j < 8; j++)
            #pragma unroll
            for (int s = 0; s < 4; s++) acc[i][j][s] = 0.f;

    int gid = lane >> 2, tid = lane & 3;

    for (int c = 0; c < NCH; c++) {
        int st = c % NSTG;
        cp_wait2();
        __syncthreads();

        uint32_t sa = base_u + st * STG_B;
        uint32_t sbb = sa + A_BYTES;
        #pragma unroll
        for (int ks = 0; ks < 4; ks++) {
            uint32_t a[2][4];
            #pragma unroll
            for (int i = 0; i < 2; i++) {
                int r = wm * 32 + i * 16 + (lane & 15);
                int g = 2 * ks + (lane >> 4);
                ldmx4(a[i], sa + r * ROWB + ((g ^ (r & 7)) << 4));
            }
            uint32_t b[8][2];
            #pragma unroll
            for (int j = 0; j < 4; j++) {
                int nt = 2 * j + ((lane >> 4) & 1);
                int n = wn * 64 + nt * 8 + (lane & 7);
                int g = 2 * ks + ((lane >> 3) & 1);
                uint32_t r4[4];
                ldmx4(r4, sbb + n * ROWB + ((g ^ (n & 7)) << 4));
                b[2*j][0] = r4[0]; b[2*j][1] = r4[1];
                b[2*j+1][0] = r4[2]; b[2*j+1][1] = r4[3];
            }
            #pragma unroll
            for (int i = 0; i < 2; i++)
                #pragma unroll
                for (int j = 0; j < 8; j++)
                    mma_f16(acc[i][j], a[i], b[j]);
        }
        __syncthreads();
        if (c + 3 < NCH) issue(c + 3, st);
        cp_commit();   // empty groups keep wait_group arithmetic uniform (in-order retire)
    }

    // Epilogue: c0,c1 @ row gid; c2,c3 @ row gid+8; cols 2*tid
    #pragma unroll
    for (int i = 0; i < 2; i++) {
        #pragma unroll
        for (int h = 0; h < 2; h++) {
            int mloc = wm * 32 + i * 16 + h * 8 + gid;
            const float* cr = g_ctx + (size_t)segrow[mloc] * E_;
            float* orow = out + (size_t)(m0 + mloc) * E_;
            #pragma unroll
            for (int j = 0; j < 8; j++) {
                int col = e0 + wn * 64 + j * 8 + tid * 2;
                float2 bv = *(const float2*)(proj_b + col);
                float2 cv = *(const float2*)(cr + col);
                float2 o;
                o.x = acc[i][j][h*2+0] + bv.x + cv.x;
                o.y = acc[i][j][h*2+1] + bv.y + cv.y;
                *(float2*)(orow + col) = o;
            }
        }
    }
}

// ---------------------------------------------------------------------------
extern "C" void kernel_launch(void* const* d_in, const int* in_sizes, int n_in,
                              void* d_out, int out_size) {
    const float* x      = (const float*)d_in[0];
    const int*   cidx   = (const int*)d_in[1];
    const float* proj_w = (const float*)d_in[2];
    const float* proj_b = (const float*)d_in[3];
    const float* ctx_w  = (const float*)d_in[4];
    const float* ctx_b  = (const float*)d_in[5];
    float*       out    = (float*)d_out;

    __half* xh; cudaGetSymbolAddress((void**)&xh, g_xh);
    __half* bh; cudaGetSymbolAddress((void**)&bh, g_Bh);

    k_tohalf<<<(B_*C_*H_*W_)/2048, 256>>>(x, xh);          // 0
    k_tohalf<<<(E_*K_)/2048, 256>>>(proj_w, bh);           // 1
    k_xbar<<<2*B_*C_, 256>>>();                            // 2
    k_seg<<<NSEG, 256>>>(cidx);                            // 3
    k_mu3<<<(NSEG*E_)/8, 256>>>(proj_w, proj_b);           // 4
    k_ctx4<<<(NSEG*E_)/8, 256>>>(ctx_w, ctx_b);            // 5

    cudaFuncSetAttribute(k_gemm_mma, cudaFuncAttributeMaxDynamicSharedMemorySize, NSTG*STG_B);
    k_gemm_mma<<<dim3(E_/BN, M_/BM), 256, NSTG*STG_B>>>(cidx, proj_b, out);  // 6
}

// round 15
// speedup vs baseline: 1.3333x; 1.0313x over previous
#include <cuda_runtime.h>
#include <cuda_fp16.h>
#include <cstdint>

// Problem constants
#define B_      32
#define C_      8
#define H_      224
#define W_      224
#define E_      768
#define P_      16
#define HP_     14
#define NPATCH  196
#define NSEG    32
#define K_      256
#define M_      (B_*C_*NPATCH)  // 50176

// Static device scratch
__device__ __half g_xh[B_*C_*H_*W_];   // x as half
__device__ __half g_Bh[E_*K_];         // proj_w as half
__device__ float g_part[512*K_];       // per-(bc, w-half) partial pixel sums
__device__ float g_xm[NSEG*K_];        // segment-mean patch pixels
__device__ float g_mu[NSEG*E_];        // segment-mean embeddings (+proj_b)
__device__ float g_ctx[NSEG*E_];       // context vectors

// ---------------------------------------------------------------------------
static __device__ __forceinline__ uint32_t smem_u32(const void* p) {
    uint32_t a;
    asm("{ .reg .u64 t; cvta.to.shared.u64 t, %1; cvt.u32.u64 %0, t; }" : "=r"(a) : "l"(p));
    return a;
}
static __device__ __forceinline__ void cpa16(uint32_t dst, const void* src) {
    asm volatile("cp.async.cg.shared.global [%0], [%1], 16;" :: "r"(dst), "l"(src));
}
static __device__ __forceinline__ void cp_commit() {
    asm volatile("cp.async.commit_group;" ::: "memory");
}
static __device__ __forceinline__ void cp_wait2() {
    asm volatile("cp.async.wait_group 2;" ::: "memory");
}
static __device__ __forceinline__ void ldmx4(uint32_t* r, uint32_t a) {
    asm volatile("ldmatrix.sync.aligned.m8n8.x4.shared.b16 {%0,%1,%2,%3}, [%4];"
                 : "=r"(r[0]), "=r"(r[1]), "=r"(r[2]), "=r"(r[3]) : "r"(a));
}
static __device__ __forceinline__ void mma_f16(float* c, const uint32_t* a, const uint32_t* b) {
    asm volatile("mma.sync.aligned.m16n8k16.row.col.f32.f16.f16.f32 "
                 "{%0,%1,%2,%3}, {%4,%5,%6,%7}, {%8,%9}, {%0,%1,%2,%3};"
                 : "+f"(c[0]), "+f"(c[1]), "+f"(c[2]), "+f"(c[3])
                 : "r"(a[0]), "r"(a[1]), "r"(a[2]), "r"(a[3]), "r"(b[0]), "r"(b[1]));
}

// ---------------------------------------------------------------------------
// Launch 0: fused x->half conversion + patch-position partial sums.
// Grid 512 (= bc*2 + w-half z). Thread t = p*16 + q4*4 + hpg.
__global__ void k_prepx(const float* __restrict__ x) {
    int bc = blockIdx.x >> 1;
    int z  = blockIdx.x & 1;
    int t  = threadIdx.x;
    int p = t >> 4, q4 = (t >> 2) & 3, hpg = t & 3;
    const float* xb = x + (size_t)bc * H_ * W_;
    __half* xhb = g_xh + (size_t)bc * H_ * W_;
    float a0 = 0.f, a1 = 0.f, a2 = 0.f, a3 = 0.f;
    #pragma unroll
    for (int i = 0; i < 4; i++) {
        int hp = hpg + i * 4;
        if (hp < HP_) {
            int h = hp * P_ + p;
            #pragma unroll
            for (int jj = 0; jj < 7; jj++) {
                int w = (q4 + 4 * (z * 7 + jj)) * 4;
                float4 v = *(const float4*)(xb + h * W_ + w);
                __half2 h01 = __floats2half2_rn(v.x, v.y);
                __half2 h23 = __floats2half2_rn(v.z, v.w);
                uint2 pk;
                pk.x = *(uint32_t*)&h01;
                pk.y = *(uint32_t*)&h23;
                *(uint2*)(xhb + h * W_ + w) = pk;
                a0 += v.x; a1 += v.y; a2 += v.z; a3 += v.w;
            }
        }
    }
    // reduce over hpg (lanes differing in bits 0-1)
    #pragma unroll
    for (int d = 1; d < 4; d <<= 1) {
        a0 += __shfl_xor_sync(0xFFFFFFFF, a0, d);
        a1 += __shfl_xor_sync(0xFFFFFFFF, a1, d);
        a2 += __shfl_xor_sync(0xFFFFFFFF, a2, d);
        a3 += __shfl_xor_sync(0xFFFFFFFF, a3, d);
    }
    if (hpg == 0) {
        float4 o = {a0, a1, a2, a3};
        *(float4*)(g_part + (size_t)blockIdx.x * K_ + p * 16 + q4 * 4) = o;
    }
}

// Launch 1: proj_w -> half (8 elems/thread)
__global__ void k_tohalf(const float* __restrict__ src, __half* __restrict__ dst) {
    size_t i = ((size_t)blockIdx.x * 256 + threadIdx.x) * 8;
    float4 v0 = *(const float4*)(src + i);
    float4 v1 = *(const float4*)(src + i + 4);
    __half2 h[4];
    h[0] = __floats2half2_rn(v0.x, v0.y);
    h[1] = __floats2half2_rn(v0.z, v0.w);
    h[2] = __floats2half2_rn(v1.x, v1.y);
    h[3] = __floats2half2_rn(v1.z, v1.w);
    *(uint4*)(dst + i) = *(uint4*)h;
}

// Launch 2: gather-based segment means; ballot-prefix list build; batched MLP.
// Grid 32.
__global__ void k_seg(const int* __restrict__ cidx) {
    __shared__ unsigned wmask[8];
    __shared__ int list[B_*C_];
    int t = threadIdx.x, lane = t & 31, w = t >> 5;
    int seg = blockIdx.x;
    int mine = cidx[t] & (NSEG-1);     // B_*C_ == 256 == blockDim
    unsigned m = __ballot_sync(0xFFFFFFFF, mine == seg);
    if (lane == 0) wmask[w] = m;
    __syncthreads();
    int off = 0, total = 0;
    #pragma unroll
    for (int i = 0; i < 8; i++) {
        int pc = __popc(wmask[i]);
        if (i < w) off += pc;
        total += pc;
    }
    if (mine == seg)
        list[off + __popc(m & ((1u << lane) - 1))] = t;
    __syncthreads();
    // Batched gather: 16 independent load-pairs in flight per tile.
    float s = 0.f;
    for (int j0 = 0; j0 < total; j0 += 16) {
        float v[16];
        #pragma unroll
        for (int j = 0; j < 16; j++) {
            if (j0 + j < total) {
                int bc = list[j0 + j];
                v[j] = g_part[(2*bc)*K_ + t] + g_part[(2*bc+1)*K_ + t];
            } else v[j] = 0.f;
        }
        #pragma unroll
        for (int j = 0; j < 16; j++) s += v[j];
    }
    g_xm[seg*K_ + t] = s / ((float)NPATCH * fmaxf((float)total, 1.f));
}

// Launch 3: mu[s,e] = xm[s,:]@proj_w[e,:] + proj_b[e]. Warp per output.
__global__ void k_mu3(const float* __restrict__ proj_w, const float* __restrict__ proj_b) {
    int gw = (blockIdx.x * 256 + threadIdx.x) >> 5;
    int lane = threadIdx.x & 31;
    int s = gw & 31;
    int e = gw >> 5;
    const float* xm = g_xm + s * K_ + lane * 8;
    const float* wr = proj_w + (size_t)e * K_ + lane * 8;
    float4 x0 = *(const float4*)xm;
    float4 x1 = *(const float4*)(xm + 4);
    float4 w0 = *(const float4*)wr;
    float4 w1 = *(const float4*)(wr + 4);
    float acc = x0.x*w0.x + x0.y*w0.y + x0.z*w0.z + x0.w*w0.w
              + x1.x*w1.x + x1.y*w1.y + x1.z*w1.z + x1.w*w1.w;
    #pragma unroll
    for (int d = 16; d > 0; d >>= 1)
        acc += __shfl_xor_sync(0xFFFFFFFF, acc, d);
    if (lane == 0) g_mu[s * E_ + e] = acc + proj_b[e];
}

// Launch 4: ctx[s,e] = mu[s,:]@ctx_w[e,:] + ctx_b[e]. Warp per output.
__global__ void k_ctx4(const float* __restrict__ ctx_w, const float* __restrict__ ctx_b) {
    int gw = (blockIdx.x * 256 + threadIdx.x) >> 5;
    int lane = threadIdx.x & 31;
    int s = gw & 31;
    int e = gw >> 5;
    const float* mr = g_mu + s * E_;
    const float* cr = ctx_w + (size_t)e * E_;
    float acc = 0.f;
    #pragma unroll
    for (int c = 0; c < 6; c++) {         // f = c*128 + lane*4, coalesced float4
        int f = c * 128 + lane * 4;
        float4 mv = *(const float4*)(mr + f);
        float4 cv = *(const float4*)(cr + f);
        acc += mv.x*cv.x + mv.y*cv.y + mv.z*cv.z + mv.w*cv.w;
    }
    #pragma unroll
    for (int d = 16; d > 0; d >>= 1)
        acc += __shfl_xor_sync(0xFFFFFFFF, acc, d);
    if (lane == 0) g_ctx[s * E_ + e] = acc + ctx_b[e];
}

// ---------------------------------------------------------------------------
// Launch 5: FP16 mma.sync GEMM. CTA 128x128, K=256 in 4 chunks of 64.
// Stage: A 128x128B + B 128x128B = 32KB; 3 stages; XOR-swizzled 16B granules.
// (R12/R14 configuration — best measured. FROZEN this round.)
#define BM 128
#define BN 128
#define CK 64
#define NCH 4
#define ROWB 128
#define A_BYTES (BM*ROWB)     // 16384
#define STG_B (2*A_BYTES)     // 32768
#define NSTG 3

__global__ __launch_bounds__(256, 2)
void k_gemm_mma(const int* __restrict__ cidx, const float* __restrict__ proj_b,
                float* __restrict__ out) {
    extern __shared__ char dsm[];
    __shared__ int rowoff[BM];
    __shared__ int segrow[BM];

    int t = threadIdx.x;
    int lane = t & 31;
    int wid = t >> 5;
    int wm = wid >> 1, wn = wid & 1;
    int m0 = blockIdx.y * BM;
    int e0 = blockIdx.x * BN;
    uint32_t base_u = smem_u32(dsm);

    if (t < BM) {
        int m  = m0 + t;
        int b  = m / (C_ * NPATCH);
        int n  = m - b * (C_ * NPATCH);
        int c  = n / NPATCH;
        int r  = n - c * NPATCH;
        int hp = r / HP_;
        int wp = r - hp * HP_;
        rowoff[t] = ((b * C_ + c) * H_ + hp * P_) * W_ + wp * P_;
        segrow[t] = cidx[m / NPATCH] & (NSEG-1);
    }
    __syncthreads();

    // chunk c covers local k = 0..63 : pixel rows 4c..4c+3, 16 halves each.
    auto issue = [&](int c, int st) {
        uint32_t sb = base_u + st * STG_B;
        #pragma unroll
        for (int j = 0; j < 4; j++) {
            int idx = t + 256 * j;
            int row = idx >> 3, g = idx & 7;
            uint32_t sw = (uint32_t)((g ^ (row & 7)) << 4);
            const __half* pa = g_xh + rowoff[row] + (c*4 + (g >> 1)) * W_ + (g & 1) * 8;
            cpa16(sb + row * ROWB + sw, pa);
            const __half* pb = g_Bh + (size_t)(e0 + row) * K_ + c * CK + g * 8;
            cpa16(sb + A_BYTES + row * ROWB + sw, pb);
        }
    };

    issue(0, 0); cp_commit();
    issue(1, 1); cp_commit();
    issue(2, 2); cp_commit();

    float acc[2][8][4];
    #pragma unroll
    for (int i = 0; i < 2; i++)
        #pragma unroll
        for (int j = 0; j < 8; j++)
            #pragma unroll
            for (int s = 0; s < 4; s++) acc[i][j][s] = 0.f;

    int gid = lane >> 2, tid = lane & 3;

    for (int c = 0; c < NCH; c++) {
        int st = c % NSTG;
        cp_wait2();
        __syncthreads();

        uint32_t sa = base_u + st * STG_B;
        uint32_t sbb = sa + A_BYTES;
        #pragma unroll
        for (int ks = 0; ks < 4; ks++) {
            uint32_t a[2][4];
            #pragma unroll
            for (int i = 0; i < 2; i++) {
                int r = wm * 32 + i * 16 + (lane & 15);
                int g = 2 * ks + (lane >> 4);
                ldmx4(a[i], sa + r * ROWB + ((g ^ (r & 7)) << 4));
            }
            uint32_t b[8][2];
            #pragma unroll
            for (int j = 0; j < 4; j++) {
                int nt = 2 * j + ((lane >> 4) & 1);
                int n = wn * 64 + nt * 8 + (lane & 7);
                int g = 2 * ks + ((lane >> 3) & 1);
                uint32_t r4[4];
                ldmx4(r4, sbb + n * ROWB + ((g ^ (n & 7)) << 4));
                b[2*j][0] = r4[0]; b[2*j][1] = r4[1];
                b[2*j+1][0] = r4[2]; b[2*j+1][1] = r4[3];
            }
            #pragma unroll
            for (int i = 0; i < 2; i++)
                #pragma unroll
                for (int j = 0; j < 8; j++)
                    mma_f16(acc[i][j], a[i], b[j]);
        }
        __syncthreads();
        if (c + 3 < NCH) issue(c + 3, st);
        cp_commit();   // empty groups keep wait_group arithmetic uniform (in-order retire)
    }

    // Epilogue: c0,c1 @ row gid; c2,c3 @ row gid+8; cols 2*tid
    #pragma unroll
    for (int i = 0; i < 2; i++) {
        #pragma unroll
        for (int h = 0; h < 2; h++) {
            int mloc = wm * 32 + i * 16 + h * 8 + gid;
            const float* cr = g_ctx + (size_t)segrow[mloc] * E_;
            float* orow = out + (size_t)(m0 + mloc) * E_;
            #pragma unroll
            for (int j = 0; j < 8; j++) {
                int col = e0 + wn * 64 + j * 8 + tid * 2;
                float2 bv = *(const float2*)(proj_b + col);
                float2 cv = *(const float2*)(cr + col);
                float2 o;
                o.x = acc[i][j][h*2+0] + bv.x + cv.x;
                o.y = acc[i][j][h*2+1] + bv.y + cv.y;
                *(float2*)(orow + col) = o;
            }
        }
    }
}

// ---------------------------------------------------------------------------
extern "C" void kernel_launch(void* const* d_in, const int* in_sizes, int n_in,
                              void* d_out, int out_size) {
    const float* x      = (const float*)d_in[0];
    const int*   cidx   = (const int*)d_in[1];
    const float* proj_w = (const float*)d_in[2];
    const float* proj_b = (const float*)d_in[3];
    const float* ctx_w  = (const float*)d_in[4];
    const float* ctx_b  = (const float*)d_in[5];
    float*       out    = (float*)d_out;

    __half* bh; cudaGetSymbolAddress((void**)&bh, g_Bh);

    k_prepx<<<2*B_*C_, 256>>>(x);                          // 0 (fused tohalf+xbar)
    k_tohalf<<<(E_*K_)/2048, 256>>>(proj_w, bh);           // 1
    k_seg<<<NSEG, 256>>>(cidx);                            // 2
    k_mu3<<<(NSEG*E_)/8, 256>>>(proj_w, proj_b);           // 3
    k_ctx4<<<(NSEG*E_)/8, 256>>>(ctx_w, ctx_b);            // 4

    cudaFuncSetAttribute(k_gemm_mma, cudaFuncAttributeMaxDynamicSharedMemorySize, NSTG*STG_B);
    k_gemm_mma<<<dim3(E_/BN, M_/BM), 256, NSTG*STG_B>>>(cidx, proj_b, out);  // 5
}